// round 1
// baseline (speedup 1.0000x reference)
#include <cuda_runtime.h>
#include <cstdint>

#define T_TOK   2048
#define HID     2048
#define NEXP    64
#define INTER   512
#define SINTER  1024
#define TOPK    8
#define ROWS_SHARED 4096                 // 2 pseudo-experts x 2048 tokens
#define ROWS_MOE    (T_TOK*TOPK)         // 16384
#define ROWS_TOTAL  (ROWS_SHARED + ROWS_MOE)

// ---------------- device scratch (static allocations only) ----------------
__device__ float    g_logits[T_TOK*NEXP];
__device__ int      g_sel  [T_TOK*TOPK];
__device__ float    g_selw [T_TOK*TOPK];
__device__ int      g_cnt  [NEXP];
__device__ int      g_off  [NEXP];
__device__ int      g_cur  [NEXP];
__device__ int      g_tok  [ROWS_MOE];
__device__ float    g_tw   [ROWS_MOE];
__device__ int      g_rowof[T_TOK*TOPK];
__device__ float    g_H[(size_t)ROWS_TOTAL*INTER];   // ~42 MB
__device__ float    g_Y[(size_t)ROWS_TOTAL*HID];     // ~168 MB

// ---------------- helpers ----------------
__device__ __forceinline__ uint32_t f2tf(float f) {
    uint32_t o; asm("cvt.rna.tf32.f32 %0, %1;" : "=r"(o) : "f"(f)); return o;
}
__device__ __forceinline__ void mma8(float c[4], const uint32_t a[4],
                                     uint32_t b0, uint32_t b1) {
    asm volatile(
        "mma.sync.aligned.m16n8k8.row.col.f32.tf32.tf32.f32 "
        "{%0,%1,%2,%3}, {%4,%5,%6,%7}, {%8,%9}, {%0,%1,%2,%3};\n"
        : "+f"(c[0]), "+f"(c[1]), "+f"(c[2]), "+f"(c[3])
        : "r"(a[0]), "r"(a[1]), "r"(a[2]), "r"(a[3]), "r"(b0), "r"(b1));
}

// ---------------- 1) router GEMM: logits = x @ router_w^T ----------------
__global__ void router_gemm(const float* __restrict__ x, const float* __restrict__ rw) {
    __shared__ float As[32][33];
    __shared__ float Bs[32][65];
    const int tid = threadIdx.x;
    const int t0  = blockIdx.x * 32;
    const int m   = tid >> 3, nb = tid & 7;
    float acc[8] = {};
    for (int kt = 0; kt < HID; kt += 32) {
        __syncthreads();
        {   int r = tid >> 3, c = (tid & 7) * 4;
            const float4 v = *(const float4*)(x + (size_t)(t0 + r)*HID + kt + c);
            As[r][c] = v.x; As[r][c+1] = v.y; As[r][c+2] = v.z; As[r][c+3] = v.w; }
        #pragma unroll
        for (int i = 0; i < 8; i++) {
            int idx = tid + i*256; int e = idx >> 5, k = idx & 31;
            Bs[k][e] = rw[(size_t)e*HID + kt + k];
        }
        __syncthreads();
        #pragma unroll
        for (int k = 0; k < 32; k++) {
            float a = As[m][k];
            #pragma unroll
            for (int j = 0; j < 8; j++) acc[j] += a * Bs[k][nb + 8*j];
        }
    }
    #pragma unroll
    for (int j = 0; j < 8; j++) g_logits[(size_t)(t0+m)*NEXP + nb + 8*j] = acc[j];
}

// ---------------- 2) top-k + renorm (softmax over selected == renorm) ------
__global__ void zero_cnt_kernel() { if (threadIdx.x < NEXP) g_cnt[threadIdx.x] = 0; }

__global__ void topk_kernel() {
    int t = blockIdx.x * blockDim.x + threadIdx.x;
    if (t >= T_TOK) return;
    float l[NEXP];
    #pragma unroll
    for (int e = 0; e < NEXP; e++) l[e] = g_logits[(size_t)t*NEXP + e];
    float bw[TOPK]; int bi[TOPK];
    for (int i = 0; i < TOPK; i++) {
        float mv = -1e30f; int mi = 0;
        for (int e = 0; e < NEXP; e++) if (l[e] > mv) { mv = l[e]; mi = e; }
        bw[i] = mv; bi[i] = mi; l[mi] = -1e30f;
    }
    float s = 0.f, mx = bw[0], w[TOPK];
    #pragma unroll
    for (int i = 0; i < TOPK; i++) { w[i] = expf(bw[i] - mx); s += w[i]; }
    float inv = 1.f / s;
    #pragma unroll
    for (int i = 0; i < TOPK; i++) {
        g_sel [t*TOPK+i] = bi[i];
        g_selw[t*TOPK+i] = w[i]*inv;
        atomicAdd(&g_cnt[bi[i]], 1);
    }
}

// ---------------- 3) prefix-scan + scatter into expert buckets -------------
__global__ void scan_kernel() {
    int o = 0;
    for (int e = 0; e < NEXP; e++) { g_off[e] = o; g_cur[e] = o; o += g_cnt[e]; }
}
__global__ void scatter_kernel() {
    int idx = blockIdx.x*blockDim.x + threadIdx.x;
    if (idx >= T_TOK*TOPK) return;
    int t = idx >> 3;
    int e = g_sel[idx];
    int pos = atomicAdd(&g_cur[e], 1);
    g_tok[pos] = t; g_tw[pos] = g_selw[idx]; g_rowof[idx] = pos;
}

// ---------------- 4) stage 1: H = silu(X@Wg)*(X@Wu)*w (grouped, tf32) ------
// grid: (m_tile 16, slot 66, n_tile 8). slot 0,1 = shared halves; 2.. = experts
__global__ void stage1_kernel(const float* __restrict__ x,
                              const float* __restrict__ wg_,
                              const float* __restrict__ wu_,
                              const float* __restrict__ sg_,
                              const float* __restrict__ su_) {
    const int s = blockIdx.y;
    int nrows, hbase, ldb, offmoe = 0;
    const float *Bg, *Bu;
    if (s < 2) {
        nrows = T_TOK; hbase = s*T_TOK; ldb = SINTER;
        Bg = sg_ + s*INTER; Bu = su_ + s*INTER;
    } else {
        int e = s - 2;
        nrows = g_cnt[e]; offmoe = g_off[e]; hbase = ROWS_SHARED + offmoe; ldb = INTER;
        Bg = wg_ + (size_t)e*HID*INTER; Bu = wu_ + (size_t)e*HID*INTER;
    }
    const int m0 = blockIdx.x * 128;
    if (m0 >= nrows) return;
    const int n0   = blockIdx.z * 64;
    const int nloc = nrows - m0;

    __shared__ int      s_tok[128];
    __shared__ float    s_w  [128];
    __shared__ uint32_t As [128][36];
    __shared__ uint32_t Bgs[32][72];
    __shared__ uint32_t Bus[32][72];

    const int tid = threadIdx.x;
    if (tid < 128) {
        int r = m0 + tid;
        if (r < nrows) {
            if (s < 2) { s_tok[tid] = r; s_w[tid] = 1.f; }
            else       { s_tok[tid] = g_tok[offmoe + r]; s_w[tid] = g_tw[offmoe + r]; }
        } else { s_tok[tid] = -1; s_w[tid] = 0.f; }
    }
    __syncthreads();

    const int lane = tid & 31, warp = tid >> 5;
    const int wm = warp >> 1, wn = warp & 1;      // 4 x 2 warp grid
    const int l4 = lane >> 2, lq = lane & 3;
    float cg[2][4][4] = {}, cu[2][4][4] = {};

    for (int kt = 0; kt < HID; kt += 32) {
        __syncthreads();
        #pragma unroll
        for (int i = 0; i < 4; i++) {
            int idx = tid + i*256, r = idx >> 3, c = (idx & 7) << 2;
            int tk = s_tok[r];
            float4 v = make_float4(0.f,0.f,0.f,0.f);
            if (tk >= 0) v = *(const float4*)(x + (size_t)tk*HID + kt + c);
            As[r][c]=f2tf(v.x); As[r][c+1]=f2tf(v.y); As[r][c+2]=f2tf(v.z); As[r][c+3]=f2tf(v.w);
        }
        #pragma unroll
        for (int i = 0; i < 2; i++) {
            int idx = tid + i*256, k = idx >> 4, c = (idx & 15) << 2;
            const float4 vg = *(const float4*)(Bg + (size_t)(kt+k)*ldb + n0 + c);
            Bgs[k][c]=f2tf(vg.x); Bgs[k][c+1]=f2tf(vg.y); Bgs[k][c+2]=f2tf(vg.z); Bgs[k][c+3]=f2tf(vg.w);
            const float4 vu = *(const float4*)(Bu + (size_t)(kt+k)*ldb + n0 + c);
            Bus[k][c]=f2tf(vu.x); Bus[k][c+1]=f2tf(vu.y); Bus[k][c+2]=f2tf(vu.z); Bus[k][c+3]=f2tf(vu.w);
        }
        __syncthreads();
        #pragma unroll
        for (int ks = 0; ks < 4; ks++) {
            uint32_t a[2][4];
            #pragma unroll
            for (int mi = 0; mi < 2; mi++) {
                int r = wm*32 + mi*16 + l4, kk = ks*8 + lq;
                a[mi][0] = As[r][kk];   a[mi][1] = As[r+8][kk];
                a[mi][2] = As[r][kk+4]; a[mi][3] = As[r+8][kk+4];
            }
            #pragma unroll
            for (int ni = 0; ni < 4; ni++) {
                int n = wn*32 + ni*8 + l4, kk = ks*8 + lq;
                uint32_t bg0 = Bgs[kk][n], bg1 = Bgs[kk+4][n];
                uint32_t bu0 = Bus[kk][n], bu1 = Bus[kk+4][n];
                mma8(cg[0][ni], a[0], bg0, bg1);
                mma8(cg[1][ni], a[1], bg0, bg1);
                mma8(cu[0][ni], a[0], bu0, bu1);
                mma8(cu[1][ni], a[1], bu0, bu1);
            }
        }
    }
    #pragma unroll
    for (int mi = 0; mi < 2; mi++)
        #pragma unroll
        for (int ni = 0; ni < 4; ni++)
            #pragma unroll
            for (int j = 0; j < 4; j++) {
                int r = wm*32 + mi*16 + l4 + ((j >> 1) << 3);
                int c = wn*32 + ni*8 + 2*lq + (j & 1);
                if (r < nloc) {
                    float g = cg[mi][ni][j], u = cu[mi][ni][j];
                    float h = g / (1.f + __expf(-g)) * u * s_w[r];
                    g_H[(size_t)(hbase + m0 + r)*INTER + n0 + c] = h;
                }
            }
}

// ---------------- 5) stage 2: Y = H @ Wd (grouped, tf32) -------------------
// grid: (m_tile 16, slot 66, n_tile 16)
__global__ void stage2_kernel(const float* __restrict__ wd_,
                              const float* __restrict__ sd_) {
    const int s = blockIdx.y;
    int nrows, hbase; const float* Bd;
    if (s < 2) { nrows = T_TOK; hbase = s*T_TOK; Bd = sd_ + (size_t)s*INTER*HID; }
    else { int e = s-2; nrows = g_cnt[e]; hbase = ROWS_SHARED + g_off[e];
           Bd = wd_ + (size_t)e*INTER*HID; }
    const int m0 = blockIdx.x * 128;
    if (m0 >= nrows) return;
    const int n0   = blockIdx.z * 128;
    const int nloc = nrows - m0;

    __shared__ uint32_t As[128][36];
    __shared__ uint32_t Bs[32][136];
    const int tid = threadIdx.x, lane = tid & 31, warp = tid >> 5;
    const int wm = warp >> 1, wn = warp & 1;
    const int l4 = lane >> 2, lq = lane & 3;
    float cc[2][8][4] = {};

    for (int kt = 0; kt < INTER; kt += 32) {
        __syncthreads();
        #pragma unroll
        for (int i = 0; i < 4; i++) {
            int idx = tid + i*256, r = idx >> 3, c = (idx & 7) << 2;
            float4 v = make_float4(0.f,0.f,0.f,0.f);
            if (r < nloc) v = *(const float4*)(g_H + (size_t)(hbase+m0+r)*INTER + kt + c);
            As[r][c]=f2tf(v.x); As[r][c+1]=f2tf(v.y); As[r][c+2]=f2tf(v.z); As[r][c+3]=f2tf(v.w);
        }
        #pragma unroll
        for (int i = 0; i < 4; i++) {
            int idx = tid + i*256, k = idx >> 5, c = (idx & 31) << 2;
            const float4 v = *(const float4*)(Bd + (size_t)(kt+k)*HID + n0 + c);
            Bs[k][c]=f2tf(v.x); Bs[k][c+1]=f2tf(v.y); Bs[k][c+2]=f2tf(v.z); Bs[k][c+3]=f2tf(v.w);
        }
        __syncthreads();
        #pragma unroll
        for (int ks = 0; ks < 4; ks++) {
            uint32_t a[2][4];
            #pragma unroll
            for (int mi = 0; mi < 2; mi++) {
                int r = wm*32 + mi*16 + l4, kk = ks*8 + lq;
                a[mi][0] = As[r][kk];   a[mi][1] = As[r+8][kk];
                a[mi][2] = As[r][kk+4]; a[mi][3] = As[r+8][kk+4];
            }
            #pragma unroll
            for (int ni = 0; ni < 8; ni++) {
                int n = wn*64 + ni*8 + l4, kk = ks*8 + lq;
                uint32_t b0 = Bs[kk][n], b1 = Bs[kk+4][n];
                mma8(cc[0][ni], a[0], b0, b1);
                mma8(cc[1][ni], a[1], b0, b1);
            }
        }
    }
    #pragma unroll
    for (int mi = 0; mi < 2; mi++)
        #pragma unroll
        for (int ni = 0; ni < 8; ni++) {
            int r0 = wm*32 + mi*16 + l4;
            int c0 = wn*64 + ni*8 + 2*lq;
            if (r0 < nloc)
                *(float2*)(g_Y + (size_t)(hbase+m0+r0)*HID + n0 + c0) =
                    make_float2(cc[mi][ni][0], cc[mi][ni][1]);
            int r1 = r0 + 8;
            if (r1 < nloc)
                *(float2*)(g_Y + (size_t)(hbase+m0+r1)*HID + n0 + c0) =
                    make_float2(cc[mi][ni][2], cc[mi][ni][3]);
        }
}

// ---------------- 6) combine: out[t] = sum of this token's 10 Y rows -------
__global__ void combine_kernel(float* __restrict__ out) {
    const int t = blockIdx.x;
    __shared__ int rows[10];
    const int tid = threadIdx.x;
    if (tid < 8)       rows[tid] = ROWS_SHARED + g_rowof[t*TOPK + tid];
    else if (tid == 8) rows[8] = t;            // shared half 0
    else if (tid == 9) rows[9] = T_TOK + t;    // shared half 1
    __syncthreads();
    for (int c = tid*4; c < HID; c += 1024) {
        float4 acc = make_float4(0.f,0.f,0.f,0.f);
        #pragma unroll
        for (int j = 0; j < 10; j++) {
            const float4 v = *(const float4*)(g_Y + (size_t)rows[j]*HID + c);
            acc.x += v.x; acc.y += v.y; acc.z += v.z; acc.w += v.w;
        }
        *(float4*)(out + (size_t)t*HID + c) = acc;
    }
}

// ---------------- launch ----------------
extern "C" void kernel_launch(void* const* d_in, const int* in_sizes, int n_in,
                              void* d_out, int out_size) {
    const float* x  = (const float*)d_in[0];
    const float* rw = (const float*)d_in[1];
    const float* wg = (const float*)d_in[2];
    const float* wu = (const float*)d_in[3];
    const float* wd = (const float*)d_in[4];
    const float* sg = (const float*)d_in[5];
    const float* su = (const float*)d_in[6];
    const float* sd = (const float*)d_in[7];
    float* out = (float*)d_out;

    router_gemm   <<<64, 256>>>(x, rw);
    zero_cnt_kernel<<<1, 64>>>();
    topk_kernel   <<<8, 256>>>();
    scan_kernel   <<<1, 1>>>();
    scatter_kernel<<<64, 256>>>();
    stage1_kernel <<<dim3(16, 66, 8),  256>>>(x, wg, wu, sg, su);
    stage2_kernel <<<dim3(16, 66, 16), 256>>>(wd, sd);
    combine_kernel<<<2048, 256>>>(out);
}

// round 2
// speedup vs baseline: 1.5196x; 1.5196x over previous
#include <cuda_runtime.h>
#include <cstdint>

#define T_TOK   2048
#define HID     2048
#define NEXP    64
#define INTER   512
#define SINTER  1024
#define TOPK    8
#define ROWS_SHARED 4096
#define ROWS_MOE    (T_TOK*TOPK)
#define ROWS_TOTAL  (ROWS_SHARED + ROWS_MOE)

// ---------------- device scratch ----------------
__device__ float    g_logits[T_TOK*NEXP];
__device__ int      g_sel  [T_TOK*TOPK];
__device__ float    g_selw [T_TOK*TOPK];
__device__ int      g_cnt  [NEXP];
__device__ int      g_off  [NEXP];
__device__ int      g_cur  [NEXP];
__device__ int      g_tok  [ROWS_MOE];
__device__ float    g_tw   [ROWS_MOE];
__device__ int      g_rowof[T_TOK*TOPK];
__device__ float    g_H[(size_t)ROWS_TOTAL*INTER];
__device__ float    g_Y[(size_t)ROWS_TOTAL*HID];

__device__ __forceinline__ uint32_t f2tf(float f) {
    uint32_t o; asm("cvt.rna.tf32.f32 %0, %1;" : "=r"(o) : "f"(f)); return o;
}
__device__ __forceinline__ void mma8(float c[4], const uint32_t a[4],
                                     uint32_t b0, uint32_t b1) {
    asm volatile(
        "mma.sync.aligned.m16n8k8.row.col.f32.tf32.tf32.f32 "
        "{%0,%1,%2,%3}, {%4,%5,%6,%7}, {%8,%9}, {%0,%1,%2,%3};\n"
        : "+f"(c[0]), "+f"(c[1]), "+f"(c[2]), "+f"(c[3])
        : "r"(a[0]), "r"(a[1]), "r"(a[2]), "r"(a[3]), "r"(b0), "r"(b1));
}

// ---------------- 1) router GEMM ----------------
__global__ void router_gemm(const float* __restrict__ x, const float* __restrict__ rw) {
    __shared__ float As[32][33];
    __shared__ float Bs[32][65];
    const int tid = threadIdx.x;
    const int t0  = blockIdx.x * 32;
    const int m   = tid >> 3, nb = tid & 7;
    float acc[8] = {};
    for (int kt = 0; kt < HID; kt += 32) {
        __syncthreads();
        {   int r = tid >> 3, c = (tid & 7) * 4;
            const float4 v = *(const float4*)(x + (size_t)(t0 + r)*HID + kt + c);
            As[r][c] = v.x; As[r][c+1] = v.y; As[r][c+2] = v.z; As[r][c+3] = v.w; }
        #pragma unroll
        for (int i = 0; i < 8; i++) {
            int idx = tid + i*256; int e = idx >> 5, k = idx & 31;
            Bs[k][e] = rw[(size_t)e*HID + kt + k];
        }
        __syncthreads();
        #pragma unroll
        for (int k = 0; k < 32; k++) {
            float a = As[m][k];
            #pragma unroll
            for (int j = 0; j < 8; j++) acc[j] += a * Bs[k][nb + 8*j];
        }
    }
    #pragma unroll
    for (int j = 0; j < 8; j++) g_logits[(size_t)(t0+m)*NEXP + nb + 8*j] = acc[j];
}

// ---------------- 2) top-k ----------------
__global__ void zero_cnt_kernel() { if (threadIdx.x < NEXP) g_cnt[threadIdx.x] = 0; }

__global__ void topk_kernel() {
    int t = blockIdx.x * blockDim.x + threadIdx.x;
    if (t >= T_TOK) return;
    float l[NEXP];
    #pragma unroll
    for (int e = 0; e < NEXP; e++) l[e] = g_logits[(size_t)t*NEXP + e];
    float bw[TOPK]; int bi[TOPK];
    for (int i = 0; i < TOPK; i++) {
        float mv = -1e30f; int mi = 0;
        for (int e = 0; e < NEXP; e++) if (l[e] > mv) { mv = l[e]; mi = e; }
        bw[i] = mv; bi[i] = mi; l[mi] = -1e30f;
    }
    float s = 0.f, mx = bw[0], w[TOPK];
    #pragma unroll
    for (int i = 0; i < TOPK; i++) { w[i] = expf(bw[i] - mx); s += w[i]; }
    float inv = 1.f / s;
    #pragma unroll
    for (int i = 0; i < TOPK; i++) {
        g_sel [t*TOPK+i] = bi[i];
        g_selw[t*TOPK+i] = w[i]*inv;
        atomicAdd(&g_cnt[bi[i]], 1);
    }
}

// ---------------- 3) prefix scan + scatter ----------------
__global__ void scan_kernel() {
    const int i = threadIdx.x;           // 64 threads
    __shared__ int tmp[NEXP];
    int v = g_cnt[i];
    tmp[i] = v;
    __syncthreads();
    #pragma unroll
    for (int d = 1; d < NEXP; d <<= 1) {
        int o = (i >= d) ? tmp[i-d] : 0;
        __syncthreads();
        tmp[i] += o;
        __syncthreads();
    }
    int excl = tmp[i] - v;
    g_off[i] = excl; g_cur[i] = excl;
}
__global__ void scatter_kernel() {
    int idx = blockIdx.x*blockDim.x + threadIdx.x;
    if (idx >= T_TOK*TOPK) return;
    int t = idx >> 3;
    int e = g_sel[idx];
    int pos = atomicAdd(&g_cur[e], 1);
    g_tok[pos] = t; g_tw[pos] = g_selw[idx]; g_rowof[idx] = pos;
}

// ---------------- 4) stage 1 (double-buffered, 512 thr) ----------------
// grid (16, 66, 8); M=128, N=64(gate)+64(up), K-tile=32
#define S1_SMEM (1024 + 2*128*36*4 + 2*32*72*4 + 2*32*72*4)
__global__ void __launch_bounds__(512, 1)
stage1_kernel(const float* __restrict__ x,
              const float* __restrict__ wg_,
              const float* __restrict__ wu_,
              const float* __restrict__ sg_,
              const float* __restrict__ su_) {
    const int s = blockIdx.y;
    int nrows, hbase, ldb, offmoe = 0;
    const float *Bg, *Bu;
    if (s < 2) {
        nrows = T_TOK; hbase = s*T_TOK; ldb = SINTER;
        Bg = sg_ + s*INTER; Bu = su_ + s*INTER;
    } else {
        int e = s - 2;
        nrows = g_cnt[e]; offmoe = g_off[e]; hbase = ROWS_SHARED + offmoe; ldb = INTER;
        Bg = wg_ + (size_t)e*HID*INTER; Bu = wu_ + (size_t)e*HID*INTER;
    }
    const int m0 = blockIdx.x * 128;
    if (m0 >= nrows) return;
    const int n0   = blockIdx.z * 64;
    const int nloc = nrows - m0;

    extern __shared__ char smem_raw[];
    int*   s_tok = (int*)smem_raw;
    float* s_w   = (float*)(smem_raw + 512);
    typedef uint32_t AsT[128][36];
    typedef uint32_t BsT[32][72];
    AsT* As  = (AsT*)(smem_raw + 1024);
    BsT* Bgs = (BsT*)(smem_raw + 1024 + 2*128*36*4);
    BsT* Bus = (BsT*)(smem_raw + 1024 + 2*128*36*4 + 2*32*72*4);

    const int tid = threadIdx.x;
    if (tid < 128) {
        int r = m0 + tid;
        if (r < nrows) {
            if (s < 2) { s_tok[tid] = r; s_w[tid] = 1.f; }
            else       { s_tok[tid] = g_tok[offmoe + r]; s_w[tid] = g_tw[offmoe + r]; }
        } else { s_tok[tid] = -1; s_w[tid] = 0.f; }
    }
    __syncthreads();

    const int lane = tid & 31, warp = tid >> 5;
    const int wm = warp >> 2, wn = warp & 3;      // 4 x 4 warps; 32 rows x 16 cols each
    const int l4 = lane >> 2, lq = lane & 3;
    float cg[2][2][4] = {}, cu[2][2][4] = {};

    float4 ra[2], rbg, rbu;
    const int ar0 = (tid) >> 3,        ac0 = (tid & 7) << 2;
    const int ar1 = (tid + 512) >> 3,  ac1 = ac0;
    const int bk  = tid >> 4,          bc  = (tid & 15) << 2;

    auto loadT = [&](int kt) {
        int tk0 = s_tok[ar0];
        ra[0] = (tk0 >= 0) ? *(const float4*)(x + (size_t)tk0*HID + kt + ac0)
                           : make_float4(0.f,0.f,0.f,0.f);
        int tk1 = s_tok[ar1];
        ra[1] = (tk1 >= 0) ? *(const float4*)(x + (size_t)tk1*HID + kt + ac1)
                           : make_float4(0.f,0.f,0.f,0.f);
        rbg = *(const float4*)(Bg + (size_t)(kt + bk)*ldb + n0 + bc);
        rbu = *(const float4*)(Bu + (size_t)(kt + bk)*ldb + n0 + bc);
    };
    auto storeT = [&](int buf) {
        As[buf][ar0][ac0]=f2tf(ra[0].x); As[buf][ar0][ac0+1]=f2tf(ra[0].y);
        As[buf][ar0][ac0+2]=f2tf(ra[0].z); As[buf][ar0][ac0+3]=f2tf(ra[0].w);
        As[buf][ar1][ac1]=f2tf(ra[1].x); As[buf][ar1][ac1+1]=f2tf(ra[1].y);
        As[buf][ar1][ac1+2]=f2tf(ra[1].z); As[buf][ar1][ac1+3]=f2tf(ra[1].w);
        Bgs[buf][bk][bc]=f2tf(rbg.x); Bgs[buf][bk][bc+1]=f2tf(rbg.y);
        Bgs[buf][bk][bc+2]=f2tf(rbg.z); Bgs[buf][bk][bc+3]=f2tf(rbg.w);
        Bus[buf][bk][bc]=f2tf(rbu.x); Bus[buf][bk][bc+1]=f2tf(rbu.y);
        Bus[buf][bk][bc+2]=f2tf(rbu.z); Bus[buf][bk][bc+3]=f2tf(rbu.w);
    };
    auto comp = [&](int buf) {
        #pragma unroll
        for (int ks = 0; ks < 4; ks++) {
            const int kk = ks*8 + lq;
            uint32_t a[2][4];
            #pragma unroll
            for (int mi = 0; mi < 2; mi++) {
                int r = wm*32 + mi*16 + l4;
                a[mi][0] = As[buf][r][kk];   a[mi][1] = As[buf][r+8][kk];
                a[mi][2] = As[buf][r][kk+4]; a[mi][3] = As[buf][r+8][kk+4];
            }
            #pragma unroll
            for (int ni = 0; ni < 2; ni++) {
                int n = wn*16 + ni*8 + l4;
                uint32_t bg0 = Bgs[buf][kk][n], bg1 = Bgs[buf][kk+4][n];
                uint32_t bu0 = Bus[buf][kk][n], bu1 = Bus[buf][kk+4][n];
                mma8(cg[0][ni], a[0], bg0, bg1);
                mma8(cg[1][ni], a[1], bg0, bg1);
                mma8(cu[0][ni], a[0], bu0, bu1);
                mma8(cu[1][ni], a[1], bu0, bu1);
            }
        }
    };

    loadT(0); storeT(0); __syncthreads();
    #pragma unroll 1
    for (int kt = 0, it = 0; kt < HID; kt += 32, it++) {
        int buf = it & 1;
        if (kt + 32 < HID) loadT(kt + 32);
        comp(buf);
        if (kt + 32 < HID) { storeT(buf ^ 1); __syncthreads(); }
    }

    #pragma unroll
    for (int mi = 0; mi < 2; mi++)
        #pragma unroll
        for (int ni = 0; ni < 2; ni++)
            #pragma unroll
            for (int j = 0; j < 4; j++) {
                int r = wm*32 + mi*16 + l4 + ((j >> 1) << 3);
                int c = wn*16 + ni*8 + 2*lq + (j & 1);
                if (r < nloc) {
                    float g = cg[mi][ni][j], u = cu[mi][ni][j];
                    float h = g / (1.f + __expf(-g)) * u * s_w[r];
                    g_H[(size_t)(hbase + m0 + r)*INTER + n0 + c] = h;
                }
            }
}

// ---------------- 5) stage 2 (double-buffered, 512 thr) ----------------
// grid (16, 66, 16); M=128, N=128, K-tile=32
#define S2_SMEM (2*128*36*4 + 2*32*136*4)
__global__ void __launch_bounds__(512, 1)
stage2_kernel(const float* __restrict__ wd_,
              const float* __restrict__ sd_) {
    const int s = blockIdx.y;
    int nrows, hbase; const float* Bd;
    if (s < 2) { nrows = T_TOK; hbase = s*T_TOK; Bd = sd_ + (size_t)s*INTER*HID; }
    else { int e = s-2; nrows = g_cnt[e]; hbase = ROWS_SHARED + g_off[e];
           Bd = wd_ + (size_t)e*INTER*HID; }
    const int m0 = blockIdx.x * 128;
    if (m0 >= nrows) return;
    const int n0   = blockIdx.z * 128;
    const int nloc = nrows - m0;

    extern __shared__ char smem_raw[];
    typedef uint32_t AsT[128][36];
    typedef uint32_t BsT[32][136];
    AsT* As = (AsT*)smem_raw;
    BsT* Bs = (BsT*)(smem_raw + 2*128*36*4);

    const int tid = threadIdx.x, lane = tid & 31, warp = tid >> 5;
    const int wm = warp >> 2, wn = warp & 3;    // 4x4: 32 rows x 32 cols per warp
    const int l4 = lane >> 2, lq = lane & 3;
    float cc[2][4][4] = {};

    float4 ra[2], rb[2];
    const int ar0 = tid >> 3,         ac0 = (tid & 7) << 2;
    const int ar1 = (tid + 512) >> 3, ac1 = ac0;
    const int bk0 = tid >> 5,         bc0 = (tid & 31) << 2;
    const int bk1 = (tid + 512) >> 5, bc1 = bc0;

    auto loadT = [&](int kt) {
        ra[0] = (ar0 < nloc) ? *(const float4*)(g_H + (size_t)(hbase+m0+ar0)*INTER + kt + ac0)
                             : make_float4(0.f,0.f,0.f,0.f);
        ra[1] = (ar1 < nloc) ? *(const float4*)(g_H + (size_t)(hbase+m0+ar1)*INTER + kt + ac1)
                             : make_float4(0.f,0.f,0.f,0.f);
        rb[0] = *(const float4*)(Bd + (size_t)(kt + bk0)*HID + n0 + bc0);
        rb[1] = *(const float4*)(Bd + (size_t)(kt + bk1)*HID + n0 + bc1);
    };
    auto storeT = [&](int buf) {
        As[buf][ar0][ac0]=f2tf(ra[0].x); As[buf][ar0][ac0+1]=f2tf(ra[0].y);
        As[buf][ar0][ac0+2]=f2tf(ra[0].z); As[buf][ar0][ac0+3]=f2tf(ra[0].w);
        As[buf][ar1][ac1]=f2tf(ra[1].x); As[buf][ar1][ac1+1]=f2tf(ra[1].y);
        As[buf][ar1][ac1+2]=f2tf(ra[1].z); As[buf][ar1][ac1+3]=f2tf(ra[1].w);
        Bs[buf][bk0][bc0]=f2tf(rb[0].x); Bs[buf][bk0][bc0+1]=f2tf(rb[0].y);
        Bs[buf][bk0][bc0+2]=f2tf(rb[0].z); Bs[buf][bk0][bc0+3]=f2tf(rb[0].w);
        Bs[buf][bk1][bc1]=f2tf(rb[1].x); Bs[buf][bk1][bc1+1]=f2tf(rb[1].y);
        Bs[buf][bk1][bc1+2]=f2tf(rb[1].z); Bs[buf][bk1][bc1+3]=f2tf(rb[1].w);
    };
    auto comp = [&](int buf) {
        #pragma unroll
        for (int ks = 0; ks < 4; ks++) {
            const int kk = ks*8 + lq;
            uint32_t a[2][4];
            #pragma unroll
            for (int mi = 0; mi < 2; mi++) {
                int r = wm*32 + mi*16 + l4;
                a[mi][0] = As[buf][r][kk];   a[mi][1] = As[buf][r+8][kk];
                a[mi][2] = As[buf][r][kk+4]; a[mi][3] = As[buf][r+8][kk+4];
            }
            #pragma unroll
            for (int ni = 0; ni < 4; ni++) {
                int n = wn*32 + ni*8 + l4;
                uint32_t b0 = Bs[buf][kk][n], b1 = Bs[buf][kk+4][n];
                mma8(cc[0][ni], a[0], b0, b1);
                mma8(cc[1][ni], a[1], b0, b1);
            }
        }
    };

    loadT(0); storeT(0); __syncthreads();
    #pragma unroll 1
    for (int kt = 0, it = 0; kt < INTER; kt += 32, it++) {
        int buf = it & 1;
        if (kt + 32 < INTER) loadT(kt + 32);
        comp(buf);
        if (kt + 32 < INTER) { storeT(buf ^ 1); __syncthreads(); }
    }

    #pragma unroll
    for (int mi = 0; mi < 2; mi++)
        #pragma unroll
        for (int ni = 0; ni < 4; ni++) {
            int r0 = wm*32 + mi*16 + l4;
            int c0 = wn*32 + ni*8 + 2*lq;
            if (r0 < nloc)
                *(float2*)(g_Y + (size_t)(hbase+m0+r0)*HID + n0 + c0) =
                    make_float2(cc[mi][ni][0], cc[mi][ni][1]);
            int r1 = r0 + 8;
            if (r1 < nloc)
                *(float2*)(g_Y + (size_t)(hbase+m0+r1)*HID + n0 + c0) =
                    make_float2(cc[mi][ni][2], cc[mi][ni][3]);
        }
}

// ---------------- 6) combine ----------------
__global__ void combine_kernel(float* __restrict__ out) {
    const int t = blockIdx.x;
    __shared__ int rows[10];
    const int tid = threadIdx.x;
    if (tid < 8)       rows[tid] = ROWS_SHARED + g_rowof[t*TOPK + tid];
    else if (tid == 8) rows[8] = t;
    else if (tid == 9) rows[9] = T_TOK + t;
    __syncthreads();
    for (int c = tid*4; c < HID; c += 1024) {
        float4 acc = make_float4(0.f,0.f,0.f,0.f);
        #pragma unroll
        for (int j = 0; j < 10; j++) {
            const float4 v = *(const float4*)(g_Y + (size_t)rows[j]*HID + c);
            acc.x += v.x; acc.y += v.y; acc.z += v.z; acc.w += v.w;
        }
        *(float4*)(out + (size_t)t*HID + c) = acc;
    }
}

// ---------------- launch ----------------
extern "C" void kernel_launch(void* const* d_in, const int* in_sizes, int n_in,
                              void* d_out, int out_size) {
    const float* x  = (const float*)d_in[0];
    const float* rw = (const float*)d_in[1];
    const float* wg = (const float*)d_in[2];
    const float* wu = (const float*)d_in[3];
    const float* wd = (const float*)d_in[4];
    const float* sg = (const float*)d_in[5];
    const float* su = (const float*)d_in[6];
    const float* sd = (const float*)d_in[7];
    float* out = (float*)d_out;

    static bool attr_done = false;
    if (!attr_done) {
        cudaFuncSetAttribute(stage1_kernel, cudaFuncAttributeMaxDynamicSharedMemorySize, S1_SMEM);
        cudaFuncSetAttribute(stage2_kernel, cudaFuncAttributeMaxDynamicSharedMemorySize, S2_SMEM);
        attr_done = true;
    }

    router_gemm   <<<64, 256>>>(x, rw);
    zero_cnt_kernel<<<1, 64>>>();
    topk_kernel   <<<8, 256>>>();
    scan_kernel   <<<1, 64>>>();
    scatter_kernel<<<64, 256>>>();
    stage1_kernel <<<dim3(16, 66, 8),  512, S1_SMEM>>>(x, wg, wu, sg, su);
    stage2_kernel <<<dim3(16, 66, 16), 512, S2_SMEM>>>(wd, sd);
    combine_kernel<<<2048, 256>>>(out);
}